// round 11
// baseline (speedup 1.0000x reference)
#include <cuda_runtime.h>
#include <cuda_bf16.h>
#include <math.h>
#include <stdint.h>

// ---------------- problem constants ----------------
#define S    256
#define Dm   2048
#define NH   16
#define DH   128
#define MLPD 8192
#define INPUT_D 4096
#define EPS  1e-5f
#define THREADS 512

// ---------------- scratch ----------------
__device__ float g_x  [S * Dm];
__device__ float g_h  [S * Dm];
__device__ float g_q  [S * Dm];
__device__ float g_k  [S * Dm];
__device__ float g_v  [S * Dm];
__device__ float g_att[NH * S * S];
__device__ float g_m  [S * MLPD];
__device__ float g_split[4 * S * Dm];

// ---------------- bf16 split helpers ----------------
__device__ __forceinline__ float bhi(float x) { return __bfloat162float(__float2bfloat16(x)); }
__device__ __forceinline__ unsigned pack2(float a, float b) {
    __nv_bfloat162 t = __floats2bfloat162_rn(a, b);
    return *(unsigned*)&t;
}
__device__ __forceinline__ unsigned packlo(float a, float b) {
    return pack2(a - bhi(a), b - bhi(b));
}
__device__ __forceinline__ void mma_bf16(float* c, const unsigned* a, const unsigned* b) {
    asm volatile(
        "mma.sync.aligned.m16n8k16.row.col.f32.bf16.bf16.f32 "
        "{%0,%1,%2,%3}, {%4,%5,%6,%7}, {%8,%9}, {%0,%1,%2,%3};\n"
        : "+f"(c[0]), "+f"(c[1]), "+f"(c[2]), "+f"(c[3])
        : "r"(a[0]), "r"(a[1]), "r"(a[2]), "r"(a[3]), "r"(b[0]), "r"(b[1]));
}
__device__ __forceinline__ void ldm4(unsigned* r, uint32_t addr) {
    asm volatile("ldmatrix.sync.aligned.m8n8.x4.shared.b16 {%0,%1,%2,%3}, [%4];"
                 : "=r"(r[0]), "=r"(r[1]), "=r"(r[2]), "=r"(r[3]) : "r"(addr));
}
__device__ __forceinline__ void ldm4t(unsigned* r, uint32_t addr) {
    asm volatile("ldmatrix.sync.aligned.m8n8.x4.trans.shared.b16 {%0,%1,%2,%3}, [%4];"
                 : "=r"(r[0]), "=r"(r[1]), "=r"(r[2]), "=r"(r[3]) : "r"(addr));
}
__device__ __forceinline__ uint32_t smem_u32(const void* p) {
    uint32_t a;
    asm("{ .reg .u64 t; cvta.to.shared.u64 t, %1; cvt.u32.u64 %0, t; }" : "=r"(a) : "l"(p));
    return a;
}

// ---------------- smem geometry ----------------
// Tile 64x128x32.
// A planes: 64 rows x (16 data + 4 pad = 20) words.       5120 B each.
// B planes: either [k][n] 32 x (64+4=68) words (transB=0, 8704 B)
//        or [n][k] 128 x 20 words (transB=1, 10240 B). Reserve 10240.
#define LDWA 20
#define LDWB 68
#define A_PLANE 5120
#define B_PLANE 10240
#define OFF_AH 0
#define OFF_AL A_PLANE
#define OFF_BH (2 * A_PLANE)
#define OFF_BL (2 * A_PLANE + B_PLANE)
#define BUF_B  (2 * A_PLANE + 2 * B_PLANE)   // 30720
#define SMEM_BYTES (2 * BUF_B)               // 61440 -> 2 CTAs/SM

// ---- loaders: threads 0-255 handle A, 256-511 handle B ----
// A: 64 rows x 32 k; u: row u>>2, 8 floats at k (u&3)*8
__device__ __forceinline__ void ldA(const float* __restrict__ G, long ld,
                                    int m0, int kbase, int u, float4* r)
{
    const float* src = G + (long)(m0 + (u >> 2)) * ld + kbase + (u & 3) * 8;
    r[0] = *(const float4*)src;
    r[1] = *(const float4*)(src + 4);
}
__device__ __forceinline__ void stA(char* hi, char* lo, int u, const float4* r)
{
    const float* f = (const float*)r;
    const int w = (u >> 2) * LDWA + (u & 3) * 4;
    *(uint4*)(hi + 4 * w) =
        make_uint4(pack2(f[0],f[1]), pack2(f[2],f[3]), pack2(f[4],f[5]), pack2(f[6],f[7]));
    *(uint4*)(lo + 4 * w) =
        make_uint4(packlo(f[0],f[1]), packlo(f[2],f[3]), packlo(f[4],f[5]), packlo(f[6],f[7]));
}
// transB=0: B[K,N] global -> smem [k][n] natural layout. u: k=u>>3, seg=u&7 (16 n each)
__device__ __forceinline__ void ldB0(const float* __restrict__ G, long ld,
                                     int kbase, int n0, int u, float4* r)
{
    const float* src = G + (long)(kbase + (u >> 3)) * ld + n0 + (u & 7) * 16;
    #pragma unroll
    for (int i = 0; i < 4; i++) r[i] = *(const float4*)(src + 4 * i);
}
__device__ __forceinline__ void stB0(char* hi, char* lo, int u, const float4* r)
{
    const float* f = (const float*)r;
    const int w = (u >> 3) * LDWB + (u & 7) * 8;
    #pragma unroll
    for (int q = 0; q < 2; q++) {
        const float* g = f + 8 * q;
        *(uint4*)(hi + 4 * (w + 4 * q)) =
            make_uint4(pack2(g[0],g[1]), pack2(g[2],g[3]), pack2(g[4],g[5]), pack2(g[6],g[7]));
        *(uint4*)(lo + 4 * (w + 4 * q)) =
            make_uint4(packlo(g[0],g[1]), packlo(g[2],g[3]), packlo(g[4],g[5]), packlo(g[6],g[7]));
    }
}
// transB=1: B[N,K] global -> smem [n][k]. u: row u>>1, 16 floats at k (u&1)*16
__device__ __forceinline__ void ldB1(const float* __restrict__ G, long ld,
                                     int kbase, int n0, int u, float4* r)
{
    const float* src = G + (long)(n0 + (u >> 1)) * ld + kbase + (u & 1) * 16;
    #pragma unroll
    for (int i = 0; i < 4; i++) r[i] = *(const float4*)(src + 4 * i);
}
__device__ __forceinline__ void stB1(char* hi, char* lo, int u, const float4* r)
{
    const float* f = (const float*)r;
    const int w = (u >> 1) * LDWA + (u & 1) * 8;
    #pragma unroll
    for (int q = 0; q < 2; q++) {
        const float* g = f + 8 * q;
        *(uint4*)(hi + 4 * (w + 4 * q)) =
            make_uint4(pack2(g[0],g[1]), pack2(g[2],g[3]), pack2(g[4],g[5]), pack2(g[6],g[7]));
        *(uint4*)(lo + 4 * (w + 4 * q)) =
            make_uint4(packlo(g[0],g[1]), packlo(g[2],g[3]), packlo(g[4],g[5]), packlo(g[6],g[7]));
    }
}

// ================= bf16 3-mma GEMM, tile 64x128x32, 16 warps 4x4 =================
// modes: 0 store | 1 posemb | 2 gelu | 3 accumulate | -1 raw (splitK)
__global__ void __launch_bounds__(THREADS, 2) tgemm_k(
    const float* __restrict__ A, const float* __restrict__ B, float* __restrict__ C,
    int M, int N, int K, int lda, int ldb, int ldc,
    long batchA, long batchB, long batchC,
    const float* __restrict__ bias, long biasBatch,
    float scale, int mode, int transB, int splitK,
    int qkv, const float* __restrict__ B1, const float* __restrict__ B2,
    float* C1, float* C2,
    const float* __restrict__ bias1, const float* __restrict__ bias2)
{
    extern __shared__ char smc[];
    const uint32_t sbase = smem_u32(smc);

    int z = blockIdx.z;
    if (qkv) {
        const int sel = z >> 4;
        z &= 15;
        if (sel == 1)      { B = B1; C = C1; bias = bias1; }
        else if (sel == 2) { B = B2; C = C2; bias = bias2; }
    }
    if (splitK > 1) {
        const int Kc = K / splitK;
        A += (long)z * Kc;
        B += transB ? (long)z * Kc : (long)z * Kc * ldb;
        C += (long)z * M * N;
        ldc = N; K = Kc; bias = nullptr; mode = -1;
    } else {
        A += (long)z * batchA;
        B += (long)z * batchB;
        C += (long)z * batchC;
        if (bias) bias += (long)z * biasBatch;
    }

    const int m0 = blockIdx.y * 64;
    const int n0 = blockIdx.x * 128;
    const int tid  = threadIdx.x;
    const int lane = tid & 31;
    const int warp = tid >> 5;
    const int wm = warp >> 2;          // 0..3 (16 rows each)
    const int wn = warp & 3;           // 0..3 (32 cols each)
    const int lr = lane >> 2;
    const int lc = lane & 3;
    const bool isA = (tid < 256);
    const int u = tid & 255;

    float acc[4][4];
    #pragma unroll
    for (int j = 0; j < 4; j++)
        #pragma unroll
        for (int r = 0; r < 4; r++) acc[j][r] = 0.f;

    // A fragment offset (non-trans ldmatrix, one m16 tile per warp)
    const int arow = (lane & 7) + ((lane >> 3) & 1) * 8;
    const int akw  = ((lane >> 4) & 1) * 4;
    const uint32_t aOff = ((wm * 16 + arow) * LDWA + akw) * 4;
    // B fragment offsets:
    // transB=0: trans ldmatrix on [k][n]: row k = lane&15, word col += (lane>>4)*4
    const int btr = lane & 15;
    const int btc = (lane >> 4) * 4;
    // transB=1: non-trans ldmatrix on [n][k]
    const int brow = (lane & 7) + ((lane >> 4) & 1) * 8;
    const int bkw  = ((lane >> 3) & 1) * 4;
    uint32_t b1Off[2];
    #pragma unroll
    for (int p = 0; p < 2; p++)
        b1Off[p] = ((wn * 32 + p * 16 + brow) * LDWA + bkw) * 4;

    float4 rr[4];
    const int nCh = K >> 5;

    // prologue: chunk 0 -> regs -> buf0
    if (isA) {
        ldA(A, lda, m0, 0, u, rr);
        stA(smc + OFF_AH, smc + OFF_AL, u, rr);
    } else if (transB) {
        ldB1(B, ldb, 0, n0, u, rr);
        stB1(smc + OFF_BH, smc + OFF_BL, u, rr);
    } else {
        ldB0(B, ldb, 0, n0, u, rr);
        stB0(smc + OFF_BH, smc + OFF_BL, u, rr);
    }

    for (int c = 0; c < nCh; c++) {
        __syncthreads();
        const int rbuf = c & 1;
        const bool more = (c + 1 < nCh);

        if (more) {
            const int kb = (c + 1) * 32;
            if (isA) ldA(A, lda, m0, kb, u, rr);
            else if (transB) ldB1(B, ldb, kb, n0, u, rr);
            else     ldB0(B, ldb, kb, n0, u, rr);
        }

        const uint32_t bb = sbase + rbuf * BUF_B;
        #pragma unroll
        for (int s = 0; s < 2; s++) {
            unsigned aH[4], aL[4], bH[2][4], bL[2][4];
            ldm4(aH, bb + OFF_AH + aOff + s * 32);
            ldm4(aL, bb + OFF_AL + aOff + s * 32);
            if (!transB) {
                #pragma unroll
                for (int p = 0; p < 2; p++) {
                    const uint32_t o = ((s * 16 + btr) * LDWB + wn * 16 + p * 8 + btc) * 4;
                    ldm4t(bH[p], bb + OFF_BH + o);
                    ldm4t(bL[p], bb + OFF_BL + o);
                }
            } else {
                #pragma unroll
                for (int p = 0; p < 2; p++) {
                    ldm4(bH[p], bb + OFF_BH + b1Off[p] + s * 32);
                    ldm4(bL[p], bb + OFF_BL + b1Off[p] + s * 32);
                }
            }
            #pragma unroll
            for (int nt = 0; nt < 4; nt++)
                mma_bf16(acc[nt], aH, &bH[nt >> 1][(nt & 1) * 2]);
            #pragma unroll
            for (int nt = 0; nt < 4; nt++)
                mma_bf16(acc[nt], aL, &bH[nt >> 1][(nt & 1) * 2]);
            #pragma unroll
            for (int nt = 0; nt < 4; nt++)
                mma_bf16(acc[nt], aH, &bL[nt >> 1][(nt & 1) * 2]);
        }

        if (more) {
            char* wb = smc + (rbuf ^ 1) * BUF_B;
            if (isA) stA(wb + OFF_AH, wb + OFF_AL, u, rr);
            else if (transB) stB1(wb + OFF_BH, wb + OFF_BL, u, rr);
            else     stB0(wb + OFF_BH, wb + OFF_BL, u, rr);
        }
    }

    // ---- epilogue: warp tile 16x32 ----
    #pragma unroll
    for (int nt = 0; nt < 4; nt++) {
        #pragma unroll
        for (int half = 0; half < 2; half++) {
            const int r = m0 + wm * 16 + lr + half * 8;
            const int cbase = n0 + wn * 32 + nt * 8 + lc * 2;
            #pragma unroll
            for (int j = 0; j < 2; j++) {
                const int n = cbase + j;
                const float raw = acc[nt][half * 2 + j];
                float* cp = C + (long)r * ldc + n;
                if (mode == -1) { *cp = raw; continue; }
                float val = raw * scale + (bias ? bias[n] : 0.0f);
                if (mode == 0) *cp = val;
                else if (mode == 1) {
                    const int   even = ((n & 1) == 0);
                    const float expo = (even ? (float)n : (float)(n - 1)) / (float)Dm;
                    const float ang  = (float)r / powf(10000.0f, expo);
                    *cp = val + (even ? sinf(ang) : cosf(ang));
                } else if (mode == 2) {
                    *cp = 0.5f * val * (1.0f + erff(val * 0.70710678118654752f));
                } else {
                    *cp += val;
                }
            }
        }
    }
}

// ---------------- split-K reduce + epilogue ----------------
__global__ __launch_bounds__(256) void reduce_k(
    const float* __restrict__ part, float* __restrict__ C,
    const float* __restrict__ bias, int M, int N, int ldc,
    int splitK, float scale, int mode)
{
    const int idx = blockIdx.x * 256 + threadIdx.x;
    if (idx >= M * N) return;
    const int m = idx / N;
    const int n = idx - m * N;
    float s = 0.f;
    for (int p = 0; p < splitK; p++) s += part[(long)p * M * N + idx];
    float val = s * scale + (bias ? bias[n] : 0.0f);
    float* cp = C + (long)m * ldc + n;
    if (mode == 0) *cp = val;
    else if (mode == 1) {
        const int   even = ((n & 1) == 0);
        const float expo = (even ? (float)n : (float)(n - 1)) / (float)Dm;
        const float ang  = (float)m / powf(10000.0f, expo);
        *cp = val + (even ? sinf(ang) : cosf(ang));
    } else if (mode == 2) {
        *cp = 0.5f * val * (1.0f + erff(val * 0.70710678118654752f));
    } else {
        *cp += val;
    }
}

// ---------------- layernorm ----------------
__global__ __launch_bounds__(256) void layernorm_k(
    const float* __restrict__ x, float* __restrict__ y,
    const float* __restrict__ g, const float* __restrict__ b)
{
    const int row = blockIdx.x;
    const float* xr = x + (long)row * Dm;
    const int t = threadIdx.x;
    __shared__ float red[256];

    float loc[8];
    float s = 0.f;
    #pragma unroll
    for (int i = 0; i < 8; i++) { loc[i] = xr[t + i * 256]; s += loc[i]; }
    red[t] = s; __syncthreads();
    for (int st = 128; st > 0; st >>= 1) { if (t < st) red[t] += red[t + st]; __syncthreads(); }
    const float mean = red[0] * (1.0f / Dm);
    __syncthreads();

    float vs = 0.f;
    #pragma unroll
    for (int i = 0; i < 8; i++) { float d = loc[i] - mean; vs += d * d; }
    red[t] = vs; __syncthreads();
    for (int st = 128; st > 0; st >>= 1) { if (t < st) red[t] += red[t + st]; __syncthreads(); }
    const float inv = rsqrtf(red[0] * (1.0f / Dm) + EPS);

    float* yr = y + (long)row * Dm;
    #pragma unroll
    for (int i = 0; i < 8; i++) {
        const int c = t + i * 256;
        yr[c] = (loc[i] - mean) * inv * g[c] + b[c];
    }
}

// ---------------- softmax (rows of 256) ----------------
__global__ __launch_bounds__(256) void softmax_k(float* __restrict__ att)
{
    const int row = blockIdx.x;
    float* p = att + (long)row * 256;
    const int t = threadIdx.x;
    __shared__ float red[256];

    float v = p[t];
    red[t] = v; __syncthreads();
    for (int st = 128; st > 0; st >>= 1) { if (t < st) red[t] = fmaxf(red[t], red[t + st]); __syncthreads(); }
    const float mx = red[0];
    __syncthreads();

    float e = expf(v - mx);
    red[t] = e; __syncthreads();
    for (int st = 128; st > 0; st >>= 1) { if (t < st) red[t] += red[t + st]; __syncthreads(); }
    p[t] = e / red[0];
}

// ---------------- head ----------------
__global__ __launch_bounds__(256) void head_k(
    const float* __restrict__ x, const float* __restrict__ hw,
    const float* __restrict__ hb, const float* __restrict__ mem,
    float* __restrict__ out, int memN)
{
    const int t = threadIdx.x;
    __shared__ float red[256];
    float s = 0.f;
    for (int i = t; i < Dm; i += 256) s += x[i] * hw[i];
    red[t] = s; __syncthreads();
    for (int st = 128; st > 0; st >>= 1) { if (t < st) red[t] += red[t + st]; __syncthreads(); }
    if (t == 0) {
        float zv = red[0] + hb[0];
        out[0] = 1.0f / (1.0f + expf(-zv));
    }
    if (t >= 1 && t <= memN) out[t] = mem[t - 1];
}

// ---------------- host launcher ----------------
static inline float* symaddr(const void* sym) {
    void* p = nullptr;
    cudaGetSymbolAddress(&p, sym);
    return (float*)p;
}

extern "C" void kernel_launch(void* const* d_in, const int* in_sizes, int n_in,
                              void* d_out, int out_size)
{
    const float* images = (const float*)d_in[0];
    const float* memory = (const float*)d_in[1];
    const float* wmap   = (const float*)d_in[2];
    const float* bmap   = (const float*)d_in[3];
    const float* ln1_g  = (const float*)d_in[4];
    const float* ln1_b  = (const float*)d_in[5];
    const float* qw     = (const float*)d_in[6];
    const float* qb     = (const float*)d_in[7];
    const float* kw     = (const float*)d_in[8];
    const float* kb     = (const float*)d_in[9];
    const float* vw     = (const float*)d_in[10];
    const float* vb     = (const float*)d_in[11];
    const float* ln2_g  = (const float*)d_in[12];
    const float* ln2_b  = (const float*)d_in[13];
    const float* w1     = (const float*)d_in[14];
    const float* b1     = (const float*)d_in[15];
    const float* w2     = (const float*)d_in[16];
    const float* b2     = (const float*)d_in[17];
    const float* head_w = (const float*)d_in[18];
    const float* head_b = (const float*)d_in[19];
    float* out = (float*)d_out;

    float* x   = symaddr(g_x);
    float* h   = symaddr(g_h);
    float* q   = symaddr(g_q);
    float* k   = symaddr(g_k);
    float* v   = symaddr(g_v);
    float* att = symaddr(g_att);
    float* m   = symaddr(g_m);
    float* ws  = symaddr(g_split);

    cudaFuncSetAttribute(tgemm_k, cudaFuncAttributeMaxDynamicSharedMemorySize, SMEM_BYTES);

    const float attScale = 1.0f / sqrtf((float)DH);

    // ---- patch embed (split-K=4): 16 x 4 x 4 = 256 CTAs ----
    tgemm_k<<<dim3(Dm / 128, S / 64, 4), THREADS, SMEM_BYTES>>>(
        images, wmap, ws, S, Dm, INPUT_D, INPUT_D, Dm, Dm,
        0, 0, 0, nullptr, 0, 1.0f, 0, 0, 4,
        0, nullptr, nullptr, nullptr, nullptr, nullptr, nullptr);
    reduce_k<<<(S * Dm + 255) / 256, 256>>>(ws, x, bmap, S, Dm, Dm, 4, 1.0f, 1);

    for (int l = 0; l < 2; l++) {
        const long wOff  = (long)l * NH * DH * DH;
        const long bOff  = (long)l * Dm;
        const long w1Off = (long)l * Dm * MLPD;
        const long w2Off = (long)l * MLPD * Dm;

        layernorm_k<<<S, 256>>>(x, h, ln1_g + bOff, ln1_b + bOff);

        // fused q,k,v: 1 x 4 x 48 = 192 CTAs
        tgemm_k<<<dim3(DH / 128, S / 64, 3 * NH), THREADS, SMEM_BYTES>>>(
            h, qw + wOff, q, S, DH, DH, Dm, DH, Dm,
            DH, (long)DH * DH, DH, qb + bOff, DH, 1.0f, 0, 0, 1,
            1, kw + wOff, vw + wOff, k, v, kb + bOff, vb + bOff);

        // scores = q @ k^T / sqrt(DH): 2 x 4 x 16 = 128 CTAs
        tgemm_k<<<dim3(S / 128, S / 64, NH), THREADS, SMEM_BYTES>>>(
            q, k, att, S, S, DH, Dm, Dm, S,
            DH, DH, (long)S * S, nullptr, 0, attScale, 0, 1, 1,
            0, nullptr, nullptr, nullptr, nullptr, nullptr, nullptr);

        softmax_k<<<NH * S, 256>>>(att);

        // x += att @ v: 1 x 4 x 16 = 64 CTAs
        tgemm_k<<<dim3(DH / 128, S / 64, NH), THREADS, SMEM_BYTES>>>(
            att, v, x, S, DH, S, S, Dm, Dm,
            (long)S * S, DH, DH, nullptr, 0, 1.0f, 3, 0, 1,
            0, nullptr, nullptr, nullptr, nullptr, nullptr, nullptr);

        layernorm_k<<<S, 256>>>(x, h, ln2_g + bOff, ln2_b + bOff);

        // m = gelu(h @ w1 + b1): 64 x 4 = 256 CTAs
        tgemm_k<<<dim3(MLPD / 128, S / 64, 1), THREADS, SMEM_BYTES>>>(
            h, w1 + w1Off, m, S, MLPD, Dm, Dm, MLPD, MLPD,
            0, 0, 0, b1 + (long)l * MLPD, 0, 1.0f, 2, 0, 1,
            0, nullptr, nullptr, nullptr, nullptr, nullptr, nullptr);

        // x += m @ w2 + b2: split-K=4 -> 16 x 4 x 4 = 256 CTAs
        tgemm_k<<<dim3(Dm / 128, S / 64, 4), THREADS, SMEM_BYTES>>>(
            m, w2 + w2Off, ws, S, Dm, MLPD, MLPD, Dm, Dm,
            0, 0, 0, nullptr, 0, 1.0f, 0, 0, 4,
            0, nullptr, nullptr, nullptr, nullptr, nullptr, nullptr);
        reduce_k<<<(S * Dm + 255) / 256, 256>>>(ws, x, b2 + bOff, S, Dm, Dm, 4, 1.0f, 3);
    }

    int memN = in_sizes[1];
    if (memN > out_size - 1) memN = out_size - 1;
    head_k<<<1, 256>>>(x, head_w, head_b, memory, out, memN);
}

// round 12
// speedup vs baseline: 1.0337x; 1.0337x over previous
#include <cuda_runtime.h>
#include <cuda_bf16.h>
#include <math.h>
#include <stdint.h>

// ---------------- problem constants ----------------
#define S    256
#define Dm   2048
#define NH   16
#define DH   128
#define MLPD 8192
#define INPUT_D 4096
#define EPS  1e-5f
#define THREADS 512

// ---------------- scratch ----------------
__device__ float g_x  [S * Dm];
__device__ float g_h  [S * Dm];
__device__ float g_q  [S * Dm];
__device__ float g_k  [S * Dm];
__device__ float g_v  [S * Dm];
__device__ float g_att[NH * S * S];
__device__ float g_m  [S * MLPD];
__device__ float g_split[4 * S * Dm];

// ---------------- bf16 split helpers ----------------
__device__ __forceinline__ float bhi(float x) { return __bfloat162float(__float2bfloat16(x)); }
__device__ __forceinline__ unsigned pack2(float a, float b) {
    __nv_bfloat162 t = __floats2bfloat162_rn(a, b);
    return *(unsigned*)&t;
}
__device__ __forceinline__ unsigned packlo(float a, float b) {
    return pack2(a - bhi(a), b - bhi(b));
}
__device__ __forceinline__ void mma_bf16(float* c, const unsigned* a, const unsigned* b) {
    asm volatile(
        "mma.sync.aligned.m16n8k16.row.col.f32.bf16.bf16.f32 "
        "{%0,%1,%2,%3}, {%4,%5,%6,%7}, {%8,%9}, {%0,%1,%2,%3};\n"
        : "+f"(c[0]), "+f"(c[1]), "+f"(c[2]), "+f"(c[3])
        : "r"(a[0]), "r"(a[1]), "r"(a[2]), "r"(a[3]), "r"(b[0]), "r"(b[1]));
}
__device__ __forceinline__ void ldm4(unsigned* r, uint32_t addr) {
    asm volatile("ldmatrix.sync.aligned.m8n8.x4.shared.b16 {%0,%1,%2,%3}, [%4];"
                 : "=r"(r[0]), "=r"(r[1]), "=r"(r[2]), "=r"(r[3]) : "r"(addr));
}
__device__ __forceinline__ void ldm4t(unsigned* r, uint32_t addr) {
    asm volatile("ldmatrix.sync.aligned.m8n8.x4.trans.shared.b16 {%0,%1,%2,%3}, [%4];"
                 : "=r"(r[0]), "=r"(r[1]), "=r"(r[2]), "=r"(r[3]) : "r"(addr));
}
__device__ __forceinline__ uint32_t smem_u32(const void* p) {
    uint32_t a;
    asm("{ .reg .u64 t; cvta.to.shared.u64 t, %1; cvt.u32.u64 %0, t; }" : "=r"(a) : "l"(p));
    return a;
}

// ---------------- smem geometry ----------------
// Tile 128x128x32, double buffered.
// A planes: [m][k] 128 rows x (16 data + 4 pad = 20) words = 10240 B.
// B planes: transB=0 -> [k][n] 32 rows x (64 data + 2 pad... use 132) words = 16896 B
//           transB=1 -> [n][k] 128 rows x 20 words = 10240 B (fits in same plane)
#define LDWA 20
#define LDWB 132
#define A_PLANE 10240
#define B_PLANE 16896
#define OFF_AH 0
#define OFF_AL A_PLANE
#define OFF_BH (2 * A_PLANE)
#define OFF_BL (2 * A_PLANE + B_PLANE)
#define BUF_B  (2 * A_PLANE + 2 * B_PLANE)   // 54272
#define SMEM_BYTES (2 * BUF_B)               // 108544

// ---- loaders: threads 0-255 handle A, 256-511 handle B ----
// A: 128 rows x 32 k; u: row u>>1, 16 floats at (u&1)*16
__device__ __forceinline__ void ldA(const float* __restrict__ G, long ld,
                                    int m0, int kbase, int u, float4* r)
{
    const float* src = G + (long)(m0 + (u >> 1)) * ld + kbase + (u & 1) * 16;
    #pragma unroll
    for (int i = 0; i < 4; i++) r[i] = *(const float4*)(src + 4 * i);
}
__device__ __forceinline__ void stA(char* hi, char* lo, int u, const float4* r)
{
    const float* f = (const float*)r;
    const int w = (u >> 1) * LDWA + (u & 1) * 8;
    *(uint4*)(hi + 4 * w) =
        make_uint4(pack2(f[0],f[1]), pack2(f[2],f[3]), pack2(f[4],f[5]), pack2(f[6],f[7]));
    *(uint4*)(hi + 4 * (w + 4)) =
        make_uint4(pack2(f[8],f[9]), pack2(f[10],f[11]), pack2(f[12],f[13]), pack2(f[14],f[15]));
    *(uint4*)(lo + 4 * w) =
        make_uint4(packlo(f[0],f[1]), packlo(f[2],f[3]), packlo(f[4],f[5]), packlo(f[6],f[7]));
    *(uint4*)(lo + 4 * (w + 4)) =
        make_uint4(packlo(f[8],f[9]), packlo(f[10],f[11]), packlo(f[12],f[13]), packlo(f[14],f[15]));
}
// transB=0: B[K,N] global -> smem natural [k][n]. u: k = u>>3 (0..31), seg = u&7 (16 n each)
__device__ __forceinline__ void ldB0(const float* __restrict__ G, long ld,
                                     int kbase, int n0, int u, float4* r)
{
    const float* src = G + (long)(kbase + (u >> 3)) * ld + n0 + (u & 7) * 16;
    #pragma unroll
    for (int i = 0; i < 4; i++) r[i] = *(const float4*)(src + 4 * i);
}
__device__ __forceinline__ void stB0(char* hi, char* lo, int u, const float4* r)
{
    const float* f = (const float*)r;
    const int w = (u >> 3) * LDWB + (u & 7) * 8;
    #pragma unroll
    for (int q = 0; q < 2; q++) {
        const float* g = f + 8 * q;
        *(uint4*)(hi + 4 * (w + 4 * q)) =
            make_uint4(pack2(g[0],g[1]), pack2(g[2],g[3]), pack2(g[4],g[5]), pack2(g[6],g[7]));
        *(uint4*)(lo + 4 * (w + 4 * q)) =
            make_uint4(packlo(g[0],g[1]), packlo(g[2],g[3]), packlo(g[4],g[5]), packlo(g[6],g[7]));
    }
}
// transB=1: B[N,K] global -> smem [n][k] (same pattern as A)
__device__ __forceinline__ void ldB1(const float* __restrict__ G, long ld,
                                     int kbase, int n0, int u, float4* r)
{
    const float* src = G + (long)(n0 + (u >> 1)) * ld + kbase + (u & 1) * 16;
    #pragma unroll
    for (int i = 0; i < 4; i++) r[i] = *(const float4*)(src + 4 * i);
}
__device__ __forceinline__ void stB1(char* hi, char* lo, int u, const float4* r)
{
    const float* f = (const float*)r;
    const int w = (u >> 1) * LDWA + (u & 1) * 8;
    *(uint4*)(hi + 4 * w) =
        make_uint4(pack2(f[0],f[1]), pack2(f[2],f[3]), pack2(f[4],f[5]), pack2(f[6],f[7]));
    *(uint4*)(hi + 4 * (w + 4)) =
        make_uint4(pack2(f[8],f[9]), pack2(f[10],f[11]), pack2(f[12],f[13]), pack2(f[14],f[15]));
    *(uint4*)(lo + 4 * w) =
        make_uint4(packlo(f[0],f[1]), packlo(f[2],f[3]), packlo(f[4],f[5]), packlo(f[6],f[7]));
    *(uint4*)(lo + 4 * (w + 4)) =
        make_uint4(packlo(f[8],f[9]), packlo(f[10],f[11]), packlo(f[12],f[13]), packlo(f[14],f[15]));
}

// ================= bf16 3-mma GEMM, tile 128x128x32, 16 warps 4x4 =================
// modes: 0 store | 1 posemb | 2 gelu | 3 accumulate | -1 raw (splitK)
__global__ void __launch_bounds__(THREADS, 1) tgemm_k(
    const float* __restrict__ A, const float* __restrict__ B, float* __restrict__ C,
    int M, int N, int K, int lda, int ldb, int ldc,
    long batchA, long batchB, long batchC,
    const float* __restrict__ bias, long biasBatch,
    float scale, int mode, int transB, int splitK,
    int qkv, const float* __restrict__ B1, const float* __restrict__ B2,
    float* C1, float* C2,
    const float* __restrict__ bias1, const float* __restrict__ bias2)
{
    extern __shared__ char smc[];
    const uint32_t sbase = smem_u32(smc);

    int z = blockIdx.z;
    if (qkv) {
        const int sel = z >> 4;
        z &= 15;
        if (sel == 1)      { B = B1; C = C1; bias = bias1; }
        else if (sel == 2) { B = B2; C = C2; bias = bias2; }
    }
    if (splitK > 1) {
        const int Kc = K / splitK;
        A += (long)z * Kc;
        B += transB ? (long)z * Kc : (long)z * Kc * ldb;
        C += (long)z * M * N;
        ldc = N; K = Kc; bias = nullptr; mode = -1;
    } else {
        A += (long)z * batchA;
        B += (long)z * batchB;
        C += (long)z * batchC;
        if (bias) bias += (long)z * biasBatch;
    }

    const int m0 = blockIdx.y * 128;
    const int n0 = blockIdx.x * 128;
    const int tid  = threadIdx.x;
    const int lane = tid & 31;
    const int warp = tid >> 5;
    const int wm = warp >> 2;          // 0..3 (32 rows each)
    const int wn = warp & 3;           // 0..3 (32 cols each)
    const int lr = lane >> 2;
    const int lc = lane & 3;
    const bool isA = (tid < 256);
    const int u = tid & 255;

    float acc[2][4][4];
    #pragma unroll
    for (int i = 0; i < 2; i++)
        #pragma unroll
        for (int j = 0; j < 4; j++)
            #pragma unroll
            for (int r = 0; r < 4; r++) acc[i][j][r] = 0.f;

    // A fragment offsets (non-trans ldmatrix, two m16 tiles per warp)
    uint32_t aOff[2];
    {
        const int arow = (lane & 7) + ((lane >> 3) & 1) * 8;
        const int akw  = ((lane >> 4) & 1) * 4;
        #pragma unroll
        for (int mt = 0; mt < 2; mt++)
            aOff[mt] = ((wm * 32 + mt * 16 + arow) * LDWA + akw) * 4;
    }
    // B fragment offsets
    // transB=0: trans ldmatrix on [k][n]: rows k = lane&15, col words (lane>>4)*4
    const int btr = lane & 15;
    const int btc = (lane >> 4) * 4;
    // transB=1: non-trans ldmatrix on [n][k]
    uint32_t b1Off[2];
    {
        const int brow = (lane & 7) + ((lane >> 4) & 1) * 8;
        const int bkw  = ((lane >> 3) & 1) * 4;
        #pragma unroll
        for (int p = 0; p < 2; p++)
            b1Off[p] = ((wn * 32 + p * 16 + brow) * LDWA + bkw) * 4;
    }

    float4 rr[4];
    const int nCh = K >> 5;

    // prologue: chunk 0 -> regs -> buf0
    if (isA) {
        ldA(A, lda, m0, 0, u, rr);
        stA(smc + OFF_AH, smc + OFF_AL, u, rr);
    } else if (transB) {
        ldB1(B, ldb, 0, n0, u, rr);
        stB1(smc + OFF_BH, smc + OFF_BL, u, rr);
    } else {
        ldB0(B, ldb, 0, n0, u, rr);
        stB0(smc + OFF_BH, smc + OFF_BL, u, rr);
    }

    for (int c = 0; c < nCh; c++) {
        __syncthreads();
        const int rbuf = c & 1;
        const bool more = (c + 1 < nCh);

        if (more) {
            const int kb = (c + 1) * 32;
            if (isA) ldA(A, lda, m0, kb, u, rr);
            else if (transB) ldB1(B, ldb, kb, n0, u, rr);
            else     ldB0(B, ldb, kb, n0, u, rr);
        }

        const uint32_t bb = sbase + rbuf * BUF_B;
        #pragma unroll
        for (int s = 0; s < 2; s++) {
            unsigned aH[2][4], aL[2][4], bH[2][4], bL[2][4];
            #pragma unroll
            for (int mt = 0; mt < 2; mt++) {
                ldm4(aH[mt], bb + OFF_AH + aOff[mt] + s * 32);
                ldm4(aL[mt], bb + OFF_AL + aOff[mt] + s * 32);
            }
            if (!transB) {
                #pragma unroll
                for (int p = 0; p < 2; p++) {
                    const uint32_t o = ((s * 16 + btr) * LDWB + wn * 16 + p * 8 + btc) * 4;
                    ldm4t(bH[p], bb + OFF_BH + o);
                    ldm4t(bL[p], bb + OFF_BL + o);
                }
            } else {
                #pragma unroll
                for (int p = 0; p < 2; p++) {
                    ldm4(bH[p], bb + OFF_BH + b1Off[p] + s * 32);
                    ldm4(bL[p], bb + OFF_BL + b1Off[p] + s * 32);
                }
            }
            #pragma unroll
            for (int mt = 0; mt < 2; mt++)
                #pragma unroll
                for (int nt = 0; nt < 4; nt++)
                    mma_bf16(acc[mt][nt], aH[mt], &bH[nt >> 1][(nt & 1) * 2]);
            #pragma unroll
            for (int mt = 0; mt < 2; mt++)
                #pragma unroll
                for (int nt = 0; nt < 4; nt++)
                    mma_bf16(acc[mt][nt], aL[mt], &bH[nt >> 1][(nt & 1) * 2]);
            #pragma unroll
            for (int mt = 0; mt < 2; mt++)
                #pragma unroll
                for (int nt = 0; nt < 4; nt++)
                    mma_bf16(acc[mt][nt], aH[mt], &bL[nt >> 1][(nt & 1) * 2]);
        }

        if (more) {
            char* wb = smc + (rbuf ^ 1) * BUF_B;
            if (isA) stA(wb + OFF_AH, wb + OFF_AL, u, rr);
            else if (transB) stB1(wb + OFF_BH, wb + OFF_BL, u, rr);
            else     stB0(wb + OFF_BH, wb + OFF_BL, u, rr);
        }
    }

    // ---- epilogue: warp tile 32x32 ----
    #pragma unroll
    for (int mt = 0; mt < 2; mt++) {
        #pragma unroll
        for (int nt = 0; nt < 4; nt++) {
            #pragma unroll
            for (int half = 0; half < 2; half++) {
                const int r = m0 + wm * 32 + mt * 16 + lr + half * 8;
                const int cbase = n0 + wn * 32 + nt * 8 + lc * 2;
                #pragma unroll
                for (int j = 0; j < 2; j++) {
                    const int n = cbase + j;
                    const float raw = acc[mt][nt][half * 2 + j];
                    float* cp = C + (long)r * ldc + n;
                    if (mode == -1) { *cp = raw; continue; }
                    float val = raw * scale + (bias ? bias[n] : 0.0f);
                    if (mode == 0) *cp = val;
                    else if (mode == 1) {
                        const int   even = ((n & 1) == 0);
                        const float expo = (even ? (float)n : (float)(n - 1)) / (float)Dm;
                        const float ang  = (float)r / powf(10000.0f, expo);
                        *cp = val + (even ? sinf(ang) : cosf(ang));
                    } else if (mode == 2) {
                        *cp = 0.5f * val * (1.0f + erff(val * 0.70710678118654752f));
                    } else {
                        *cp += val;
                    }
                }
            }
        }
    }
}

// ---------------- split-K reduce + epilogue ----------------
__global__ __launch_bounds__(256) void reduce_k(
    const float* __restrict__ part, float* __restrict__ C,
    const float* __restrict__ bias, int M, int N, int ldc,
    int splitK, float scale, int mode)
{
    const int idx = blockIdx.x * 256 + threadIdx.x;
    if (idx >= M * N) return;
    const int m = idx / N;
    const int n = idx - m * N;
    float s = 0.f;
    for (int p = 0; p < splitK; p++) s += part[(long)p * M * N + idx];
    float val = s * scale + (bias ? bias[n] : 0.0f);
    float* cp = C + (long)m * ldc + n;
    if (mode == 0) *cp = val;
    else if (mode == 1) {
        const int   even = ((n & 1) == 0);
        const float expo = (even ? (float)n : (float)(n - 1)) / (float)Dm;
        const float ang  = (float)m / powf(10000.0f, expo);
        *cp = val + (even ? sinf(ang) : cosf(ang));
    } else if (mode == 2) {
        *cp = 0.5f * val * (1.0f + erff(val * 0.70710678118654752f));
    } else {
        *cp += val;
    }
}

// ---------------- layernorm ----------------
__global__ __launch_bounds__(256) void layernorm_k(
    const float* __restrict__ x, float* __restrict__ y,
    const float* __restrict__ g, const float* __restrict__ b)
{
    const int row = blockIdx.x;
    const float* xr = x + (long)row * Dm;
    const int t = threadIdx.x;
    __shared__ float red[256];

    float loc[8];
    float s = 0.f;
    #pragma unroll
    for (int i = 0; i < 8; i++) { loc[i] = xr[t + i * 256]; s += loc[i]; }
    red[t] = s; __syncthreads();
    for (int st = 128; st > 0; st >>= 1) { if (t < st) red[t] += red[t + st]; __syncthreads(); }
    const float mean = red[0] * (1.0f / Dm);
    __syncthreads();

    float vs = 0.f;
    #pragma unroll
    for (int i = 0; i < 8; i++) { float d = loc[i] - mean; vs += d * d; }
    red[t] = vs; __syncthreads();
    for (int st = 128; st > 0; st >>= 1) { if (t < st) red[t] += red[t + st]; __syncthreads(); }
    const float inv = rsqrtf(red[0] * (1.0f / Dm) + EPS);

    float* yr = y + (long)row * Dm;
    #pragma unroll
    for (int i = 0; i < 8; i++) {
        const int c = t + i * 256;
        yr[c] = (loc[i] - mean) * inv * g[c] + b[c];
    }
}

// ---------------- softmax (rows of 256) ----------------
__global__ __launch_bounds__(256) void softmax_k(float* __restrict__ att)
{
    const int row = blockIdx.x;
    float* p = att + (long)row * 256;
    const int t = threadIdx.x;
    __shared__ float red[256];

    float v = p[t];
    red[t] = v; __syncthreads();
    for (int st = 128; st > 0; st >>= 1) { if (t < st) red[t] = fmaxf(red[t], red[t + st]); __syncthreads(); }
    const float mx = red[0];
    __syncthreads();

    float e = expf(v - mx);
    red[t] = e; __syncthreads();
    for (int st = 128; st > 0; st >>= 1) { if (t < st) red[t] += red[t + st]; __syncthreads(); }
    p[t] = e / red[0];
}

// ---------------- head ----------------
__global__ __launch_bounds__(256) void head_k(
    const float* __restrict__ x, const float* __restrict__ hw,
    const float* __restrict__ hb, const float* __restrict__ mem,
    float* __restrict__ out, int memN)
{
    const int t = threadIdx.x;
    __shared__ float red[256];
    float s = 0.f;
    for (int i = t; i < Dm; i += 256) s += x[i] * hw[i];
    red[t] = s; __syncthreads();
    for (int st = 128; st > 0; st >>= 1) { if (t < st) red[t] += red[t + st]; __syncthreads(); }
    if (t == 0) {
        float zv = red[0] + hb[0];
        out[0] = 1.0f / (1.0f + expf(-zv));
    }
    if (t >= 1 && t <= memN) out[t] = mem[t - 1];
}

// ---------------- host launcher ----------------
static inline float* symaddr(const void* sym) {
    void* p = nullptr;
    cudaGetSymbolAddress(&p, sym);
    return (float*)p;
}

extern "C" void kernel_launch(void* const* d_in, const int* in_sizes, int n_in,
                              void* d_out, int out_size)
{
    const float* images = (const float*)d_in[0];
    const float* memory = (const float*)d_in[1];
    const float* wmap   = (const float*)d_in[2];
    const float* bmap   = (const float*)d_in[3];
    const float* ln1_g  = (const float*)d_in[4];
    const float* ln1_b  = (const float*)d_in[5];
    const float* qw     = (const float*)d_in[6];
    const float* qb     = (const float*)d_in[7];
    const float* kw     = (const float*)d_in[8];
    const float* kb     = (const float*)d_in[9];
    const float* vw     = (const float*)d_in[10];
    const float* vb     = (const float*)d_in[11];
    const float* ln2_g  = (const float*)d_in[12];
    const float* ln2_b  = (const float*)d_in[13];
    const float* w1     = (const float*)d_in[14];
    const float* b1     = (const float*)d_in[15];
    const float* w2     = (const float*)d_in[16];
    const float* b2     = (const float*)d_in[17];
    const float* head_w = (const float*)d_in[18];
    const float* head_b = (const float*)d_in[19];
    float* out = (float*)d_out;

    float* x   = symaddr(g_x);
    float* h   = symaddr(g_h);
    float* q   = symaddr(g_q);
    float* k   = symaddr(g_k);
    float* v   = symaddr(g_v);
    float* att = symaddr(g_att);
    float* m   = symaddr(g_m);
    float* ws  = symaddr(g_split);

    cudaFuncSetAttribute(tgemm_k, cudaFuncAttributeMaxDynamicSharedMemorySize, SMEM_BYTES);

    const float attScale = 1.0f / sqrtf((float)DH);

    // ---- patch embed (split-K=4): 16 x 2 x 4 = 128 CTAs ----
    tgemm_k<<<dim3(Dm / 128, S / 128, 4), THREADS, SMEM_BYTES>>>(
        images, wmap, ws, S, Dm, INPUT_D, INPUT_D, Dm, Dm,
        0, 0, 0, nullptr, 0, 1.0f, 0, 0, 4,
        0, nullptr, nullptr, nullptr, nullptr, nullptr, nullptr);
    reduce_k<<<(S * Dm + 255) / 256, 256>>>(ws, x, bmap, S, Dm, Dm, 4, 1.0f, 1);

    for (int l = 0; l < 2; l++) {
        const long wOff  = (long)l * NH * DH * DH;
        const long bOff  = (long)l * Dm;
        const long w1Off = (long)l * Dm * MLPD;
        const long w2Off = (long)l * MLPD * Dm;

        layernorm_k<<<S, 256>>>(x, h, ln1_g + bOff, ln1_b + bOff);

        // fused q,k,v: 1 x 2 x 48 = 96 CTAs
        tgemm_k<<<dim3(DH / 128, S / 128, 3 * NH), THREADS, SMEM_BYTES>>>(
            h, qw + wOff, q, S, DH, DH, Dm, DH, Dm,
            DH, (long)DH * DH, DH, qb + bOff, DH, 1.0f, 0, 0, 1,
            1, kw + wOff, vw + wOff, k, v, kb + bOff, vb + bOff);

        // scores = q @ k^T / sqrt(DH): 2 x 2 x 16 = 64 CTAs (transB=1)
        tgemm_k<<<dim3(S / 128, S / 128, NH), THREADS, SMEM_BYTES>>>(
            q, k, att, S, S, DH, Dm, Dm, S,
            DH, DH, (long)S * S, nullptr, 0, attScale, 0, 1, 1,
            0, nullptr, nullptr, nullptr, nullptr, nullptr, nullptr);

        softmax_k<<<NH * S, 256>>>(att);

        // x += att @ v: 1 x 2 x 16 = 32 CTAs
        tgemm_k<<<dim3(DH / 128, S / 128, NH), THREADS, SMEM_BYTES>>>(
            att, v, x, S, DH, S, S, Dm, Dm,
            (long)S * S, DH, DH, nullptr, 0, 1.0f, 3, 0, 1,
            0, nullptr, nullptr, nullptr, nullptr, nullptr, nullptr);

        layernorm_k<<<S, 256>>>(x, h, ln2_g + bOff, ln2_b + bOff);

        // m = gelu(h @ w1 + b1): 64 x 2 = 128 CTAs
        tgemm_k<<<dim3(MLPD / 128, S / 128, 1), THREADS, SMEM_BYTES>>>(
            h, w1 + w1Off, m, S, MLPD, Dm, Dm, MLPD, MLPD,
            0, 0, 0, b1 + (long)l * MLPD, 0, 1.0f, 2, 0, 1,
            0, nullptr, nullptr, nullptr, nullptr, nullptr, nullptr);

        // x += m @ w2 + b2: split-K=4 -> 16 x 2 x 4 = 128 CTAs
        tgemm_k<<<dim3(Dm / 128, S / 128, 4), THREADS, SMEM_BYTES>>>(
            m, w2 + w2Off, ws, S, Dm, MLPD, MLPD, Dm, Dm,
            0, 0, 0, nullptr, 0, 1.0f, 0, 0, 4,
            0, nullptr, nullptr, nullptr, nullptr, nullptr, nullptr);
        reduce_k<<<(S * Dm + 255) / 256, 256>>>(ws, x, b2 + bOff, S, Dm, Dm, 4, 1.0f, 3);
    }

    int memN = in_sizes[1];
    if (memN > out_size - 1) memN = out_size - 1;
    head_k<<<1, 256>>>(x, head_w, head_b, memory, out, memN);
}

// round 13
// speedup vs baseline: 1.1796x; 1.1411x over previous
#include <cuda_runtime.h>
#include <cuda_bf16.h>
#include <math.h>
#include <stdint.h>

// ---------------- problem constants ----------------
#define S    256
#define Dm   2048
#define NH   16
#define DH   128
#define MLPD 8192
#define INPUT_D 4096
#define EPS  1e-5f
#define THREADS 512

// ---------------- scratch ----------------
__device__ float g_x  [S * Dm];
__device__ float g_h  [S * Dm];
__device__ float g_q  [S * Dm];
__device__ float g_k  [S * Dm];
__device__ float g_v  [S * Dm];
__device__ float g_att[NH * S * S];
__device__ float g_m  [S * MLPD];
__device__ float g_split[4 * S * Dm];

// ---------------- bf16 split helpers ----------------
__device__ __forceinline__ float bhi(float x) { return __bfloat162float(__float2bfloat16(x)); }
__device__ __forceinline__ unsigned pack2(float a, float b) {
    __nv_bfloat162 t = __floats2bfloat162_rn(a, b);
    return *(unsigned*)&t;
}
__device__ __forceinline__ unsigned packlo(float a, float b) {
    return pack2(a - bhi(a), b - bhi(b));
}
__device__ __forceinline__ void mma_bf16(float* c, const unsigned* a, const unsigned* b) {
    asm volatile(
        "mma.sync.aligned.m16n8k16.row.col.f32.bf16.bf16.f32 "
        "{%0,%1,%2,%3}, {%4,%5,%6,%7}, {%8,%9}, {%0,%1,%2,%3};\n"
        : "+f"(c[0]), "+f"(c[1]), "+f"(c[2]), "+f"(c[3])
        : "r"(a[0]), "r"(a[1]), "r"(a[2]), "r"(a[3]), "r"(b[0]), "r"(b[1]));
}
__device__ __forceinline__ void ldm4(unsigned* r, uint32_t addr) {
    asm volatile("ldmatrix.sync.aligned.m8n8.x4.shared.b16 {%0,%1,%2,%3}, [%4];"
                 : "=r"(r[0]), "=r"(r[1]), "=r"(r[2]), "=r"(r[3]) : "r"(addr));
}
__device__ __forceinline__ void ldm4t(unsigned* r, uint32_t addr) {
    asm volatile("ldmatrix.sync.aligned.m8n8.x4.trans.shared.b16 {%0,%1,%2,%3}, [%4];"
                 : "=r"(r[0]), "=r"(r[1]), "=r"(r[2]), "=r"(r[3]) : "r"(addr));
}
__device__ __forceinline__ uint32_t smem_u32(const void* p) {
    uint32_t a;
    asm("{ .reg .u64 t; cvta.to.shared.u64 t, %1; cvt.u32.u64 %0, t; }" : "=r"(a) : "l"(p));
    return a;
}

// ======================================================================
// Kernel A — exact R8 body: tile 128x128x32, 16 warps (4x4, warp 32x32)
// ======================================================================
#define LWA 20
#define PLA (128 * LWA * 4)          // 10240
#define BUFA (4 * PLA)               // 40960
#define SMEM_A (2 * BUFA)            // 81920
#define AH_A 0
#define AL_A PLA
#define BH_A (2 * PLA)
#define BL_A (3 * PLA)

__device__ __forceinline__ void ldRowsA(const float* __restrict__ G, long ld,
                                        int row0, int kbase, int t, float4* r)
{
    const float* src = G + (long)(row0 + (t >> 1)) * ld + kbase + (t & 1) * 16;
    #pragma unroll
    for (int i = 0; i < 4; i++) r[i] = *(const float4*)(src + 4 * i);
}
__device__ __forceinline__ void stRowsA(char* hi, char* lo, int t, const float4* r)
{
    const float* f = (const float*)r;
    const int w = (t >> 1) * LWA + (t & 1) * 8;
    *(uint4*)(hi + 4 * w) =
        make_uint4(pack2(f[0],f[1]), pack2(f[2],f[3]), pack2(f[4],f[5]), pack2(f[6],f[7]));
    *(uint4*)(hi + 4 * (w + 4)) =
        make_uint4(pack2(f[8],f[9]), pack2(f[10],f[11]), pack2(f[12],f[13]), pack2(f[14],f[15]));
    *(uint4*)(lo + 4 * w) =
        make_uint4(packlo(f[0],f[1]), packlo(f[2],f[3]), packlo(f[4],f[5]), packlo(f[6],f[7]));
    *(uint4*)(lo + 4 * (w + 4)) =
        make_uint4(packlo(f[8],f[9]), packlo(f[10],f[11]), packlo(f[12],f[13]), packlo(f[14],f[15]));
}
__device__ __forceinline__ void ldBTA(const float* __restrict__ G, long ld,
                                      int kbase, int n0, int t, float4* r)
{
    const int kq = t >> 5;
    const int nq = t & 31;
    const float* src = G + (long)(kbase + kq * 4) * ld + n0 + nq * 4;
    #pragma unroll
    for (int i = 0; i < 4; i++) r[i] = *(const float4*)(src + (long)i * ld);
}
__device__ __forceinline__ void stBTA(char* hi, char* lo, int t, const float4* r)
{
    const int kq = t >> 5;
    const int nq = t & 31;
    const float c[4][4] = {{r[0].x, r[1].x, r[2].x, r[3].x}, {r[0].y, r[1].y, r[2].y, r[3].y},
                           {r[0].z, r[1].z, r[2].z, r[3].z}, {r[0].w, r[1].w, r[2].w, r[3].w}};
    #pragma unroll
    for (int j = 0; j < 4; j++) {
        const int w = (nq * 4 + j) * LWA + kq * 2;
        *(uint2*)(hi + 4 * w) = make_uint2(pack2(c[j][0], c[j][1]), pack2(c[j][2], c[j][3]));
        *(uint2*)(lo + 4 * w) = make_uint2(packlo(c[j][0], c[j][1]), packlo(c[j][2], c[j][3]));
    }
}

__global__ void __launch_bounds__(THREADS, 1) tgemm128_k(
    const float* __restrict__ A, const float* __restrict__ B, float* __restrict__ C,
    int M, int N, int K, int lda, int ldb, int ldc,
    long batchA, long batchB, long batchC,
    const float* __restrict__ bias, long biasBatch,
    float scale, int mode, int transB, int splitK)
{
    extern __shared__ char smc[];
    const uint32_t sbase = smem_u32(smc);

    int z = blockIdx.z;
    if (splitK > 1) {
        const int Kc = K / splitK;
        A += (long)z * Kc;
        B += transB ? (long)z * Kc : (long)z * Kc * ldb;
        C += (long)z * M * N;
        ldc = N; K = Kc; bias = nullptr; mode = -1;
    } else {
        A += (long)z * batchA;
        B += (long)z * batchB;
        C += (long)z * batchC;
        if (bias) bias += (long)z * biasBatch;
    }

    const int m0 = blockIdx.y * 128;
    const int n0 = blockIdx.x * 128;
    const int tid  = threadIdx.x;
    const int lane = tid & 31;
    const int warp = tid >> 5;
    const int wm = warp >> 2;
    const int wn = warp & 3;
    const int lr = lane >> 2;
    const int lc = lane & 3;
    const bool isA = (tid < 256);
    const int t = tid & 255;

    float acc[2][4][4];
    #pragma unroll
    for (int i = 0; i < 2; i++)
        #pragma unroll
        for (int j = 0; j < 4; j++)
            #pragma unroll
            for (int r = 0; r < 4; r++) acc[i][j][r] = 0.f;

    uint32_t aOff[2], bOff[2];
    {
        const int arow = (lane & 7) + ((lane >> 3) & 1) * 8;
        const int akw  = ((lane >> 4) & 1) * 4;
        #pragma unroll
        for (int mt = 0; mt < 2; mt++)
            aOff[mt] = ((wm * 32 + mt * 16 + arow) * LWA + akw) * 4;
        const int brow = (lane & 7) + ((lane >> 4) & 1) * 8;
        const int bkw  = ((lane >> 3) & 1) * 4;
        #pragma unroll
        for (int p = 0; p < 2; p++)
            bOff[p] = ((wn * 32 + p * 16 + brow) * LWA + bkw) * 4;
    }

    float4 rr[4];
    const int nCh = K >> 5;

    if (isA) {
        ldRowsA(A, lda, m0, 0, t, rr);
        stRowsA(smc + AH_A, smc + AL_A, t, rr);
    } else {
        if (transB) { ldRowsA(B, ldb, n0, 0, t, rr); stRowsA(smc + BH_A, smc + BL_A, t, rr); }
        else        { ldBTA(B, ldb, 0, n0, t, rr);   stBTA(smc + BH_A, smc + BL_A, t, rr); }
    }

    for (int c = 0; c < nCh; c++) {
        __syncthreads();
        const int rbuf = c & 1;
        const bool more = (c + 1 < nCh);

        if (more) {
            const int kb = (c + 1) * 32;
            if (isA) ldRowsA(A, lda, m0, kb, t, rr);
            else if (transB) ldRowsA(B, ldb, n0, kb, t, rr);
            else     ldBTA(B, ldb, kb, n0, t, rr);
        }

        const uint32_t bb = sbase + rbuf * BUFA;
        #pragma unroll
        for (int s = 0; s < 2; s++) {
            const uint32_t so = s * 32;
            unsigned aH[2][4], aL[2][4], bH[2][4], bL[2][4];
            #pragma unroll
            for (int mt = 0; mt < 2; mt++) {
                ldm4(aH[mt], bb + AH_A + aOff[mt] + so);
                ldm4(aL[mt], bb + AL_A + aOff[mt] + so);
            }
            #pragma unroll
            for (int p = 0; p < 2; p++) {
                ldm4(bH[p], bb + BH_A + bOff[p] + so);
                ldm4(bL[p], bb + BL_A + bOff[p] + so);
            }
            #pragma unroll
            for (int mt = 0; mt < 2; mt++)
                #pragma unroll
                for (int nt = 0; nt < 4; nt++) {
                    const unsigned* bh = &bH[nt >> 1][(nt & 1) * 2];
                    const unsigned* bl = &bL[nt >> 1][(nt & 1) * 2];
                    mma_bf16(acc[mt][nt], aH[mt], bh);
                    mma_bf16(acc[mt][nt], aL[mt], bh);
                    mma_bf16(acc[mt][nt], aH[mt], bl);
                }
        }

        if (more) {
            char* wb = smc + (rbuf ^ 1) * BUFA;
            if (isA) stRowsA(wb + AH_A, wb + AL_A, t, rr);
            else if (transB) stRowsA(wb + BH_A, wb + BL_A, t, rr);
            else     stBTA(wb + BH_A, wb + BL_A, t, rr);
        }
    }

    #pragma unroll
    for (int mt = 0; mt < 2; mt++) {
        #pragma unroll
        for (int nt = 0; nt < 4; nt++) {
            #pragma unroll
            for (int half = 0; half < 2; half++) {
                const int r = m0 + wm * 32 + mt * 16 + lr + half * 8;
                const int cbase = n0 + wn * 32 + nt * 8 + lc * 2;
                #pragma unroll
                for (int j = 0; j < 2; j++) {
                    const int n = cbase + j;
                    const float raw = acc[mt][nt][half * 2 + j];
                    float* cp = C + (long)r * ldc + n;
                    if (mode == -1) { *cp = raw; continue; }
                    float val = raw * scale + (bias ? bias[n] : 0.0f);
                    if (mode == 0) *cp = val;
                    else if (mode == 1) {
                        const int   even = ((n & 1) == 0);
                        const float expo = (even ? (float)n : (float)(n - 1)) / (float)Dm;
                        const float ang  = (float)r / powf(10000.0f, expo);
                        *cp = val + (even ? sinf(ang) : cosf(ang));
                    } else if (mode == 2) {
                        *cp = 0.5f * val * (1.0f + erff(val * 0.70710678118654752f));
                    } else {
                        *cp += val;
                    }
                }
            }
        }
    }
}

// ======================================================================
// Kernel B — exact R11 body: tile 64x128x32, 16 warps (4x4, warp 16x32)
// ======================================================================
#define LWA_B 20
#define LWB_B 68
#define APL_B 5120
#define BPL_B 10240
#define AH_B 0
#define AL_B APL_B
#define BH_B (2 * APL_B)
#define BL_B (2 * APL_B + BPL_B)
#define BUF_B2 (2 * APL_B + 2 * BPL_B)   // 30720
#define SMEM_B (2 * BUF_B2)              // 61440

__device__ __forceinline__ void ldA_b(const float* __restrict__ G, long ld,
                                      int m0, int kbase, int u, float4* r)
{
    const float* src = G + (long)(m0 + (u >> 2)) * ld + kbase + (u & 3) * 8;
    r[0] = *(const float4*)src;
    r[1] = *(const float4*)(src + 4);
}
__device__ __forceinline__ void stA_b(char* hi, char* lo, int u, const float4* r)
{
    const float* f = (const float*)r;
    const int w = (u >> 2) * LWA_B + (u & 3) * 4;
    *(uint4*)(hi + 4 * w) =
        make_uint4(pack2(f[0],f[1]), pack2(f[2],f[3]), pack2(f[4],f[5]), pack2(f[6],f[7]));
    *(uint4*)(lo + 4 * w) =
        make_uint4(packlo(f[0],f[1]), packlo(f[2],f[3]), packlo(f[4],f[5]), packlo(f[6],f[7]));
}
__device__ __forceinline__ void ldB0_b(const float* __restrict__ G, long ld,
                                       int kbase, int n0, int u, float4* r)
{
    const float* src = G + (long)(kbase + (u >> 3)) * ld + n0 + (u & 7) * 16;
    #pragma unroll
    for (int i = 0; i < 4; i++) r[i] = *(const float4*)(src + 4 * i);
}
__device__ __forceinline__ void stB0_b(char* hi, char* lo, int u, const float4* r)
{
    const float* f = (const float*)r;
    const int w = (u >> 3) * LWB_B + (u & 7) * 8;
    #pragma unroll
    for (int q = 0; q < 2; q++) {
        const float* g = f + 8 * q;
        *(uint4*)(hi + 4 * (w + 4 * q)) =
            make_uint4(pack2(g[0],g[1]), pack2(g[2],g[3]), pack2(g[4],g[5]), pack2(g[6],g[7]));
        *(uint4*)(lo + 4 * (w + 4 * q)) =
            make_uint4(packlo(g[0],g[1]), packlo(g[2],g[3]), packlo(g[4],g[5]), packlo(g[6],g[7]));
    }
}
__device__ __forceinline__ void ldB1_b(const float* __restrict__ G, long ld,
                                       int kbase, int n0, int u, float4* r)
{
    const float* src = G + (long)(n0 + (u >> 1)) * ld + kbase + (u & 1) * 16;
    #pragma unroll
    for (int i = 0; i < 4; i++) r[i] = *(const float4*)(src + 4 * i);
}
__device__ __forceinline__ void stB1_b(char* hi, char* lo, int u, const float4* r)
{
    const float* f = (const float*)r;
    const int w = (u >> 1) * LWA_B + (u & 1) * 8;
    #pragma unroll
    for (int q = 0; q < 2; q++) {
        const float* g = f + 8 * q;
        *(uint4*)(hi + 4 * (w + 4 * q)) =
            make_uint4(pack2(g[0],g[1]), pack2(g[2],g[3]), pack2(g[4],g[5]), pack2(g[6],g[7]));
        *(uint4*)(lo + 4 * (w + 4 * q)) =
            make_uint4(packlo(g[0],g[1]), packlo(g[2],g[3]), packlo(g[4],g[5]), packlo(g[6],g[7]));
    }
}

__global__ void __launch_bounds__(THREADS, 2) tgemm64_k(
    const float* __restrict__ A, const float* __restrict__ B, float* __restrict__ C,
    int M, int N, int K, int lda, int ldb, int ldc,
    long batchA, long batchB, long batchC,
    const float* __restrict__ bias, long biasBatch,
    float scale, int mode, int transB, int splitK,
    int qkv, const float* __restrict__ B1, const float* __restrict__ B2,
    float* C1, float* C2,
    const float* __restrict__ bias1, const float* __restrict__ bias2)
{
    extern __shared__ char smc[];
    const uint32_t sbase = smem_u32(smc);

    int z = blockIdx.z;
    if (qkv) {
        const int sel = z >> 4;
        z &= 15;
        if (sel == 1)      { B = B1; C = C1; bias = bias1; }
        else if (sel == 2) { B = B2; C = C2; bias = bias2; }
    }
    if (splitK > 1) {
        const int Kc = K / splitK;
        A += (long)z * Kc;
        B += transB ? (long)z * Kc : (long)z * Kc * ldb;
        C += (long)z * M * N;
        ldc = N; K = Kc; bias = nullptr; mode = -1;
    } else {
        A += (long)z * batchA;
        B += (long)z * batchB;
        C += (long)z * batchC;
        if (bias) bias += (long)z * biasBatch;
    }

    const int m0 = blockIdx.y * 64;
    const int n0 = blockIdx.x * 128;
    const int tid  = threadIdx.x;
    const int lane = tid & 31;
    const int warp = tid >> 5;
    const int wm = warp >> 2;
    const int wn = warp & 3;
    const int lr = lane >> 2;
    const int lc = lane & 3;
    const bool isA = (tid < 256);
    const int u = tid & 255;

    float acc[4][4];
    #pragma unroll
    for (int j = 0; j < 4; j++)
        #pragma unroll
        for (int r = 0; r < 4; r++) acc[j][r] = 0.f;

    const int arow = (lane & 7) + ((lane >> 3) & 1) * 8;
    const int akw  = ((lane >> 4) & 1) * 4;
    const uint32_t aOff = ((wm * 16 + arow) * LWA_B + akw) * 4;
    const int btr = lane & 15;
    const int btc = (lane >> 4) * 4;
    const int brow = (lane & 7) + ((lane >> 4) & 1) * 8;
    const int bkw  = ((lane >> 3) & 1) * 4;
    uint32_t b1Off[2];
    #pragma unroll
    for (int p = 0; p < 2; p++)
        b1Off[p] = ((wn * 32 + p * 16 + brow) * LWA_B + bkw) * 4;

    float4 rr[4];
    const int nCh = K >> 5;

    if (isA) {
        ldA_b(A, lda, m0, 0, u, rr);
        stA_b(smc + AH_B, smc + AL_B, u, rr);
    } else if (transB) {
        ldB1_b(B, ldb, 0, n0, u, rr);
        stB1_b(smc + BH_B, smc + BL_B, u, rr);
    } else {
        ldB0_b(B, ldb, 0, n0, u, rr);
        stB0_b(smc + BH_B, smc + BL_B, u, rr);
    }

    for (int c = 0; c < nCh; c++) {
        __syncthreads();
        const int rbuf = c & 1;
        const bool more = (c + 1 < nCh);

        if (more) {
            const int kb = (c + 1) * 32;
            if (isA) ldA_b(A, lda, m0, kb, u, rr);
            else if (transB) ldB1_b(B, ldb, kb, n0, u, rr);
            else     ldB0_b(B, ldb, kb, n0, u, rr);
        }

        const uint32_t bb = sbase + rbuf * BUF_B2;
        #pragma unroll
        for (int s = 0; s < 2; s++) {
            unsigned aH[4], aL[4], bH[2][4], bL[2][4];
            ldm4(aH, bb + AH_B + aOff + s * 32);
            ldm4(aL, bb + AL_B + aOff + s * 32);
            if (!transB) {
                #pragma unroll
                for (int p = 0; p < 2; p++) {
                    const uint32_t o = ((s * 16 + btr) * LWB_B + wn * 16 + p * 8 + btc) * 4;
                    ldm4t(bH[p], bb + BH_B + o);
                    ldm4t(bL[p], bb + BL_B + o);
                }
            } else {
                #pragma unroll
                for (int p = 0; p < 2; p++) {
                    ldm4(bH[p], bb + BH_B + b1Off[p] + s * 32);
                    ldm4(bL[p], bb + BL_B + b1Off[p] + s * 32);
                }
            }
            #pragma unroll
            for (int nt = 0; nt < 4; nt++)
                mma_bf16(acc[nt], aH, &bH[nt >> 1][(nt & 1) * 2]);
            #pragma unroll
            for (int nt = 0; nt < 4; nt++)
                mma_bf16(acc[nt], aL, &bH[nt >> 1][(nt & 1) * 2]);
            #pragma unroll
            for (int nt = 0; nt < 4; nt++)
                mma_bf16(acc[nt], aH, &bL[nt >> 1][(nt & 1) * 2]);
        }

        if (more) {
            char* wb = smc + (rbuf ^ 1) * BUF_B2;
            if (isA) stA_b(wb + AH_B, wb + AL_B, u, rr);
            else if (transB) stB1_b(wb + BH_B, wb + BL_B, u, rr);
            else     stB0_b(wb + BH_B, wb + BL_B, u, rr);
        }
    }

    #pragma unroll
    for (int nt = 0; nt < 4; nt++) {
        #pragma unroll
        for (int half = 0; half < 2; half++) {
            const int r = m0 + wm * 16 + lr + half * 8;
            const int cbase = n0 + wn * 32 + nt * 8 + lc * 2;
            #pragma unroll
            for (int j = 0; j < 2; j++) {
                const int n = cbase + j;
                const float raw = acc[nt][half * 2 + j];
                float* cp = C + (long)r * ldc + n;
                if (mode == -1) { *cp = raw; continue; }
                float val = raw * scale + (bias ? bias[n] : 0.0f);
                if (mode == 0) *cp = val;
                else if (mode == 1) {
                    const int   even = ((n & 1) == 0);
                    const float expo = (even ? (float)n : (float)(n - 1)) / (float)Dm;
                    const float ang  = (float)r / powf(10000.0f, expo);
                    *cp = val + (even ? sinf(ang) : cosf(ang));
                } else if (mode == 2) {
                    *cp = 0.5f * val * (1.0f + erff(val * 0.70710678118654752f));
                } else {
                    *cp += val;
                }
            }
        }
    }
}

// ---------------- split-K reduce + epilogue ----------------
__global__ __launch_bounds__(256) void reduce_k(
    const float* __restrict__ part, float* __restrict__ C,
    const float* __restrict__ bias, int M, int N, int ldc,
    int splitK, float scale, int mode)
{
    const int idx = blockIdx.x * 256 + threadIdx.x;
    if (idx >= M * N) return;
    const int m = idx / N;
    const int n = idx - m * N;
    float s = 0.f;
    for (int p = 0; p < splitK; p++) s += part[(long)p * M * N + idx];
    float val = s * scale + (bias ? bias[n] : 0.0f);
    float* cp = C + (long)m * ldc + n;
    if (mode == 0) *cp = val;
    else if (mode == 1) {
        const int   even = ((n & 1) == 0);
        const float expo = (even ? (float)n : (float)(n - 1)) / (float)Dm;
        const float ang  = (float)m / powf(10000.0f, expo);
        *cp = val + (even ? sinf(ang) : cosf(ang));
    } else if (mode == 2) {
        *cp = 0.5f * val * (1.0f + erff(val * 0.70710678118654752f));
    } else {
        *cp += val;
    }
}

// ---------------- layernorm ----------------
__global__ __launch_bounds__(256) void layernorm_k(
    const float* __restrict__ x, float* __restrict__ y,
    const float* __restrict__ g, const float* __restrict__ b)
{
    const int row = blockIdx.x;
    const float* xr = x + (long)row * Dm;
    const int t = threadIdx.x;
    __shared__ float red[256];

    float loc[8];
    float s = 0.f;
    #pragma unroll
    for (int i = 0; i < 8; i++) { loc[i] = xr[t + i * 256]; s += loc[i]; }
    red[t] = s; __syncthreads();
    for (int st = 128; st > 0; st >>= 1) { if (t < st) red[t] += red[t + st]; __syncthreads(); }
    const float mean = red[0] * (1.0f / Dm);
    __syncthreads();

    float vs = 0.f;
    #pragma unroll
    for (int i = 0; i < 8; i++) { float d = loc[i] - mean; vs += d * d; }
    red[t] = vs; __syncthreads();
    for (int st = 128; st > 0; st >>= 1) { if (t < st) red[t] += red[t + st]; __syncthreads(); }
    const float inv = rsqrtf(red[0] * (1.0f / Dm) + EPS);

    float* yr = y + (long)row * Dm;
    #pragma unroll
    for (int i = 0; i < 8; i++) {
        const int c = t + i * 256;
        yr[c] = (loc[i] - mean) * inv * g[c] + b[c];
    }
}

// ---------------- softmax (rows of 256) ----------------
__global__ __launch_bounds__(256) void softmax_k(float* __restrict__ att)
{
    const int row = blockIdx.x;
    float* p = att + (long)row * 256;
    const int t = threadIdx.x;
    __shared__ float red[256];

    float v = p[t];
    red[t] = v; __syncthreads();
    for (int st = 128; st > 0; st >>= 1) { if (t < st) red[t] = fmaxf(red[t], red[t + st]); __syncthreads(); }
    const float mx = red[0];
    __syncthreads();

    float e = expf(v - mx);
    red[t] = e; __syncthreads();
    for (int st = 128; st > 0; st >>= 1) { if (t < st) red[t] += red[t + st]; __syncthreads(); }
    p[t] = e / red[0];
}

// ---------------- head ----------------
__global__ __launch_bounds__(256) void head_k(
    const float* __restrict__ x, const float* __restrict__ hw,
    const float* __restrict__ hb, const float* __restrict__ mem,
    float* __restrict__ out, int memN)
{
    const int t = threadIdx.x;
    __shared__ float red[256];
    float s = 0.f;
    for (int i = t; i < Dm; i += 256) s += x[i] * hw[i];
    red[t] = s; __syncthreads();
    for (int st = 128; st > 0; st >>= 1) { if (t < st) red[t] += red[t + st]; __syncthreads(); }
    if (t == 0) {
        float zv = red[0] + hb[0];
        out[0] = 1.0f / (1.0f + expf(-zv));
    }
    if (t >= 1 && t <= memN) out[t] = mem[t - 1];
}

// ---------------- host launcher ----------------
static inline float* symaddr(const void* sym) {
    void* p = nullptr;
    cudaGetSymbolAddress(&p, sym);
    return (float*)p;
}

extern "C" void kernel_launch(void* const* d_in, const int* in_sizes, int n_in,
                              void* d_out, int out_size)
{
    const float* images = (const float*)d_in[0];
    const float* memory = (const float*)d_in[1];
    const float* wmap   = (const float*)d_in[2];
    const float* bmap   = (const float*)d_in[3];
    const float* ln1_g  = (const float*)d_in[4];
    const float* ln1_b  = (const float*)d_in[5];
    const float* qw     = (const float*)d_in[6];
    const float* qb     = (const float*)d_in[7];
    const float* kw     = (const float*)d_in[8];
    const float* kb     = (const float*)d_in[9];
    const float* vw     = (const float*)d_in[10];
    const float* vb     = (const float*)d_in[11];
    const float* ln2_g  = (const float*)d_in[12];
    const float* ln2_b  = (const float*)d_in[13];
    const float* w1     = (const float*)d_in[14];
    const float* b1     = (const float*)d_in[15];
    const float* w2     = (const float*)d_in[16];
    const float* b2     = (const float*)d_in[17];
    const float* head_w = (const float*)d_in[18];
    const float* head_b = (const float*)d_in[19];
    float* out = (float*)d_out;

    float* x   = symaddr(g_x);
    float* h   = symaddr(g_h);
    float* q   = symaddr(g_q);
    float* k   = symaddr(g_k);
    float* v   = symaddr(g_v);
    float* att = symaddr(g_att);
    float* m   = symaddr(g_m);
    float* ws  = symaddr(g_split);

    cudaFuncSetAttribute(tgemm128_k, cudaFuncAttributeMaxDynamicSharedMemorySize, SMEM_A);
    cudaFuncSetAttribute(tgemm64_k,  cudaFuncAttributeMaxDynamicSharedMemorySize, SMEM_B);

    const float attScale = 1.0f / sqrtf((float)DH);

    // ---- patch embed (split-K=4): kernel A, 128 CTAs ----
    tgemm128_k<<<dim3(Dm / 128, S / 128, 4), THREADS, SMEM_A>>>(
        images, wmap, ws, S, Dm, INPUT_D, INPUT_D, Dm, Dm,
        0, 0, 0, nullptr, 0, 1.0f, 0, 0, 4);
    reduce_k<<<(S * Dm + 255) / 256, 256>>>(ws, x, bmap, S, Dm, Dm, 4, 1.0f, 1);

    for (int l = 0; l < 2; l++) {
        const long wOff  = (long)l * NH * DH * DH;
        const long bOff  = (long)l * Dm;
        const long w1Off = (long)l * Dm * MLPD;
        const long w2Off = (long)l * MLPD * Dm;

        layernorm_k<<<S, 256>>>(x, h, ln1_g + bOff, ln1_b + bOff);

        // fused q,k,v: kernel B, 1 x 4 x 48 = 192 CTAs
        tgemm64_k<<<dim3(DH / 128, S / 64, 3 * NH), THREADS, SMEM_B>>>(
            h, qw + wOff, q, S, DH, DH, Dm, DH, Dm,
            DH, (long)DH * DH, DH, qb + bOff, DH, 1.0f, 0, 0, 1,
            1, kw + wOff, vw + wOff, k, v, kb + bOff, vb + bOff);

        // scores = q @ k^T / sqrt(DH): kernel B, 2 x 4 x 16 = 128 CTAs
        tgemm64_k<<<dim3(S / 128, S / 64, NH), THREADS, SMEM_B>>>(
            q, k, att, S, S, DH, Dm, Dm, S,
            DH, DH, (long)S * S, nullptr, 0, attScale, 0, 1, 1,
            0, nullptr, nullptr, nullptr, nullptr, nullptr, nullptr);

        softmax_k<<<NH * S, 256>>>(att);

        // x += att @ v: kernel B, 1 x 4 x 16 = 64 CTAs
        tgemm64_k<<<dim3(DH / 128, S / 64, NH), THREADS, SMEM_B>>>(
            att, v, x, S, DH, S, S, Dm, Dm,
            (long)S * S, DH, DH, nullptr, 0, 1.0f, 3, 0, 1,
            0, nullptr, nullptr, nullptr, nullptr, nullptr, nullptr);

        layernorm_k<<<S, 256>>>(x, h, ln2_g + bOff, ln2_b + bOff);

        // m = gelu(h @ w1 + b1): kernel A, 128 CTAs
        tgemm128_k<<<dim3(MLPD / 128, S / 128, 1), THREADS, SMEM_A>>>(
            h, w1 + w1Off, m, S, MLPD, Dm, Dm, MLPD, MLPD,
            0, 0, 0, b1 + (long)l * MLPD, 0, 1.0f, 2, 0, 1);

        // x += m @ w2 + b2: kernel A split-K=4, 128 CTAs
        tgemm128_k<<<dim3(Dm / 128, S / 128, 4), THREADS, SMEM_A>>>(
            m, w2 + w2Off, ws, S, Dm, MLPD, MLPD, Dm, Dm,
            0, 0, 0, nullptr, 0, 1.0f, 0, 0, 4);
        reduce_k<<<(S * Dm + 255) / 256, 256>>>(ws, x, b2 + bOff, S, Dm, Dm, 4, 1.0f, 3);
    }

    int memN = in_sizes[1];
    if (memN > out_size - 1) memN = out_size - 1;
    head_k<<<1, 256>>>(x, head_w, head_b, memory, out, memN);
}